// round 3
// baseline (speedup 1.0000x reference)
#include <cuda_runtime.h>

// ---------------------------------------------------------------------------
// HierarchUpdateMlp: 3-stage hierarchical MLP, TF32 mma.sync implementation.
//   Stage A (kernel1): 7 GEMMs -> out_1 [N, 7*128] (tf32-rounded, scratch)
//   Stage B+C (kernel2): 6 pair GEMMs -> relu -> smem -> accumulate final GEMM
//   Prepass (kernel0): round all weights to tf32 (rna) into scratch copies.
// ---------------------------------------------------------------------------

#define NPAD 50176   // >= ceil(50000/128)*128, padded scratch rows (zero-filled)

__device__ float g_out1[(size_t)NPAD * 896];   // stage-A output scratch
__device__ float g_W10r[128 * 1280];
__device__ float g_W1r[6 * 128 * 512];
__device__ float g_W2r[6 * 128 * 256];
__device__ float g_Wfr[256 * 768];

__device__ __forceinline__ unsigned f2tf(float x) {
    unsigned u;
    asm("cvt.rna.tf32.f32 %0, %1;" : "=r"(u) : "f"(x));
    return u;
}
__device__ __forceinline__ float f2tff(float x) { return __uint_as_float(f2tf(x)); }

__device__ __forceinline__ void mma8(float (&c)[4], const unsigned (&a)[4],
                                     const unsigned (&b)[2]) {
    asm volatile(
        "mma.sync.aligned.m16n8k8.row.col.f32.tf32.tf32.f32 "
        "{%0,%1,%2,%3},{%4,%5,%6,%7},{%8,%9},{%0,%1,%2,%3};\n"
        : "+f"(c[0]), "+f"(c[1]), "+f"(c[2]), "+f"(c[3])
        : "r"(a[0]), "r"(a[1]), "r"(a[2]), "r"(a[3]), "r"(b[0]), "r"(b[1]));
}

// ---------------------------------------------------------------------------
// Kernel 0: round weights to tf32 (rna) once per launch.
// ---------------------------------------------------------------------------
__global__ void round_weights_kernel(const float* __restrict__ W10,
                                     const float* __restrict__ W1,
                                     const float* __restrict__ W2,
                                     const float* __restrict__ Wf) {
    int i = blockIdx.x * blockDim.x + threadIdx.x;
    int st = gridDim.x * blockDim.x;
    for (int j = i; j < 128 * 1280; j += st) g_W10r[j] = f2tff(W10[j]);
    for (int j = i; j < 6 * 128 * 512; j += st) g_W1r[j] = f2tff(W1[j]);
    for (int j = i; j < 6 * 128 * 256; j += st) g_W2r[j] = f2tff(W2[j]);
    for (int j = i; j < 256 * 768; j += st) g_Wfr[j] = f2tff(Wf[j]);
}

// ---------------------------------------------------------------------------
// Kernel 1: stage A. grid = (ceil(N/128), 7). 256 threads.
// Each CTA: GEMM M=128, N=128, K = (g==0 ? 1280 : 512), relu, store to g_out1.
// Warp grid 4(m) x 2(n): warp tile 32x64 -> acc[2][8][4].
// smem tiles stride 36 floats: bank = (4*row + col) % 32 == lane -> no conflicts.
// ---------------------------------------------------------------------------
__global__ __launch_bounds__(256) void stage1_kernel(const float* __restrict__ upd,
                                                     const float* __restrict__ b10,
                                                     const float* __restrict__ b1,
                                                     int N) {
    __shared__ float As[128 * 36];
    __shared__ float Ws[128 * 36];

    const int tid = threadIdx.x;
    const int lane = tid & 31;
    const int warp = tid >> 5;
    const int wm = warp >> 1;  // 0..3
    const int wn = warp & 1;   // 0..1
    const int qr = lane >> 2;
    const int qc = lane & 3;
    const int g = blockIdx.y;
    const int row0 = blockIdx.x * 128;

    const int seg = tid & 7;   // which float4 within a 32-col chunk
    const int rb = tid >> 3;   // 0..31

    int K, ldW;
    const float* Wsrc;
    const float* bias;
    int j1 = 0, j2 = 0;
    if (g == 0) {
        K = 1280; ldW = 1280; Wsrc = g_W10r; bias = b10;
    } else {
        const int p1[6] = {5, 7, 8, 11, 13, 14};
        const int p2[6] = {6, 9, 10, 12, 15, 16};
        K = 512; ldW = 512;
        Wsrc = g_W1r + (size_t)(g - 1) * 128 * 512;
        bias = b1 + (g - 1) * 128;
        j1 = p1[g - 1]; j2 = p2[g - 1];
    }

    float acc[2][8][4];
#pragma unroll
    for (int i = 0; i < 2; i++)
#pragma unroll
        for (int j = 0; j < 8; j++)
#pragma unroll
            for (int k = 0; k < 4; k++) acc[i][j][k] = 0.f;

    float4 xA[4], xW[4];

    auto load_chunk = [&](int k0) {
        int joff;
        if (g == 0) joff = k0;                       // joints 0..4 contiguous
        else joff = ((k0 < 256) ? j1 : j2) * 256 + (k0 & 255);
#pragma unroll
        for (int i = 0; i < 4; i++) {
            int r = row0 + rb + i * 32;
            if (r > N - 1) r = N - 1;
            xA[i] = *(const float4*)(upd + (size_t)r * 4352 + joff + seg * 4);
            xW[i] = *(const float4*)(Wsrc + (size_t)(rb + i * 32) * ldW + k0 + seg * 4);
        }
    };
    auto store_chunk = [&]() {
#pragma unroll
        for (int i = 0; i < 4; i++) {
            float4 a = xA[i];
            a.x = f2tff(a.x); a.y = f2tff(a.y); a.z = f2tff(a.z); a.w = f2tff(a.w);
            *(float4*)&As[(rb + i * 32) * 36 + seg * 4] = a;
            *(float4*)&Ws[(rb + i * 32) * 36 + seg * 4] = xW[i];
        }
    };

    load_chunk(0);
    store_chunk();
    __syncthreads();

    const int nk = K >> 5;
    for (int kc = 0; kc < nk; kc++) {
        if (kc + 1 < nk) load_chunk((kc + 1) * 32);
#pragma unroll
        for (int k8 = 0; k8 < 4; k8++) {
            const int kk = k8 * 8;
            unsigned a[2][4], b[8][2];
#pragma unroll
            for (int mt = 0; mt < 2; mt++) {
                int r = wm * 32 + mt * 16 + qr;
                a[mt][0] = __float_as_uint(As[r * 36 + kk + qc]);
                a[mt][1] = __float_as_uint(As[(r + 8) * 36 + kk + qc]);
                a[mt][2] = __float_as_uint(As[r * 36 + kk + qc + 4]);
                a[mt][3] = __float_as_uint(As[(r + 8) * 36 + kk + qc + 4]);
            }
#pragma unroll
            for (int nt = 0; nt < 8; nt++) {
                int n = wn * 64 + nt * 8 + qr;
                b[nt][0] = __float_as_uint(Ws[n * 36 + kk + qc]);
                b[nt][1] = __float_as_uint(Ws[n * 36 + kk + qc + 4]);
            }
#pragma unroll
            for (int mt = 0; mt < 2; mt++)
#pragma unroll
                for (int nt = 0; nt < 8; nt++) mma8(acc[mt][nt], a[mt], b[nt]);
        }
        __syncthreads();
        if (kc + 1 < nk) store_chunk();
        __syncthreads();
    }

    // Epilogue: bias + relu, store tf32-rounded to g_out1[:, g*128 ..]
#pragma unroll
    for (int nt = 0; nt < 8; nt++) {
        int col = wn * 64 + nt * 8 + 2 * qc;
        float bb0 = bias[col], bb1 = bias[col + 1];
#pragma unroll
        for (int mt = 0; mt < 2; mt++) {
            int r = row0 + wm * 32 + mt * 16 + qr;
            if (r < N) {
                float2 s = make_float2(f2tff(fmaxf(acc[mt][nt][0] + bb0, 0.f)),
                                       f2tff(fmaxf(acc[mt][nt][1] + bb1, 0.f)));
                *(float2*)&g_out1[(size_t)r * 896 + g * 128 + col] = s;
            }
            if (r + 8 < N) {
                float2 s = make_float2(f2tff(fmaxf(acc[mt][nt][2] + bb0, 0.f)),
                                       f2tff(fmaxf(acc[mt][nt][3] + bb1, 0.f)));
                *(float2*)&g_out1[(size_t)(r + 8) * 896 + g * 128 + col] = s;
            }
        }
    }
}

// ---------------------------------------------------------------------------
// Kernel 2: stages B+C fused. grid = ceil(N/64). 256 threads.
// Per group g: GEMM M=64,N=128,K=256 (pair gather from g_out1) -> relu -> S2,
// then accumulate final: fAcc += S2 @ Wf[:, g*128:(g+1)*128]^T (M=64,N=256,K=128).
// Warp grid 2(m) x 4(n) for both stages.
// ---------------------------------------------------------------------------
__global__ __launch_bounds__(256) void stage23_kernel(const float* __restrict__ b2,
                                                      const float* __restrict__ bf,
                                                      float* __restrict__ out, int N) {
    extern __shared__ float sm[];
    float* S2 = sm;                    // 64*132 = 8448 floats
    float* A1s = sm + 8448;            // 64*36  = 2304 floats   (stage B)
    float* W2s = sm + 8448 + 2304;     // 128*36 = 4608 floats   (stage B)
    float* Wfs = sm + 8448;            // 256*36 = 9216 floats   (stage C, overlaps)

    const int tid = threadIdx.x;
    const int lane = tid & 31;
    const int warp = tid >> 5;
    const int wm = warp >> 2;  // 0..1
    const int wn = warp & 3;   // 0..3
    const int qr = lane >> 2;
    const int qc = lane & 3;
    const int seg = tid & 7;
    const int rb = tid >> 3;   // 0..31
    const int row0 = blockIdx.x * 64;

    const int q1[6] = {0, 1, 1, 1, 4, 4};
    const int q2[6] = {1, 2, 3, 4, 5, 6};

    float fAcc[2][8][4];
#pragma unroll
    for (int i = 0; i < 2; i++)
#pragma unroll
        for (int j = 0; j < 8; j++)
#pragma unroll
            for (int k = 0; k < 4; k++) fAcc[i][j][k] = 0.f;

    float4 rA[2], rW[4], rF[8];

    for (int gg = 0; gg < 6; gg++) {
        const float* W2g = g_W2r + (size_t)gg * 128 * 256;
        const int c1 = q1[gg] * 128, c2 = q2[gg] * 128;

        // ---------------- stage B: M=64, N=128, K=256 ----------------
        float acc2[2][4][4];
#pragma unroll
        for (int i = 0; i < 2; i++)
#pragma unroll
            for (int j = 0; j < 4; j++)
#pragma unroll
                for (int k = 0; k < 4; k++) acc2[i][j][k] = 0.f;

        auto loadB = [&](int k0) {
            int src = (k0 < 128) ? (c1 + k0) : (c2 + k0 - 128);
#pragma unroll
            for (int i = 0; i < 2; i++) {
                int r = row0 + rb + i * 32;  // padded scratch: always in-bounds
                rA[i] = *(const float4*)(g_out1 + (size_t)r * 896 + src + seg * 4);
            }
#pragma unroll
            for (int i = 0; i < 4; i++)
                rW[i] = *(const float4*)(W2g + (size_t)(rb + i * 32) * 256 + k0 + seg * 4);
        };
        auto stsB = [&]() {
#pragma unroll
            for (int i = 0; i < 2; i++)
                *(float4*)&A1s[(rb + i * 32) * 36 + seg * 4] = rA[i];
#pragma unroll
            for (int i = 0; i < 4; i++)
                *(float4*)&W2s[(rb + i * 32) * 36 + seg * 4] = rW[i];
        };

        loadB(0);
        stsB();  // safe: previous group's stage C ended with __syncthreads
        __syncthreads();
        for (int kc = 0; kc < 8; kc++) {
            if (kc + 1 < 8) loadB((kc + 1) * 32);
#pragma unroll
            for (int k8 = 0; k8 < 4; k8++) {
                const int kk = k8 * 8;
                unsigned a[2][4], b[4][2];
#pragma unroll
                for (int mt = 0; mt < 2; mt++) {
                    int r = wm * 32 + mt * 16 + qr;
                    a[mt][0] = __float_as_uint(A1s[r * 36 + kk + qc]);
                    a[mt][1] = __float_as_uint(A1s[(r + 8) * 36 + kk + qc]);
                    a[mt][2] = __float_as_uint(A1s[r * 36 + kk + qc + 4]);
                    a[mt][3] = __float_as_uint(A1s[(r + 8) * 36 + kk + qc + 4]);
                }
#pragma unroll
                for (int nt = 0; nt < 4; nt++) {
                    int n = wn * 32 + nt * 8 + qr;
                    b[nt][0] = __float_as_uint(W2s[n * 36 + kk + qc]);
                    b[nt][1] = __float_as_uint(W2s[n * 36 + kk + qc + 4]);
                }
#pragma unroll
                for (int mt = 0; mt < 2; mt++)
#pragma unroll
                    for (int nt = 0; nt < 4; nt++) mma8(acc2[mt][nt], a[mt], b[nt]);
            }
            __syncthreads();
            if (kc + 1 < 8) stsB();
            __syncthreads();
        }

        // Epilogue: bias + relu -> S2 (tf32-rounded)
#pragma unroll
        for (int nt = 0; nt < 4; nt++) {
            int col = wn * 32 + nt * 8 + 2 * qc;
            float bb0 = b2[gg * 128 + col], bb1 = b2[gg * 128 + col + 1];
#pragma unroll
            for (int mt = 0; mt < 2; mt++) {
                int r = wm * 32 + mt * 16 + qr;
                S2[r * 132 + col]       = f2tff(fmaxf(acc2[mt][nt][0] + bb0, 0.f));
                S2[r * 132 + col + 1]   = f2tff(fmaxf(acc2[mt][nt][1] + bb1, 0.f));
                S2[(r + 8) * 132 + col]     = f2tff(fmaxf(acc2[mt][nt][2] + bb0, 0.f));
                S2[(r + 8) * 132 + col + 1] = f2tff(fmaxf(acc2[mt][nt][3] + bb1, 0.f));
            }
        }

        // ---------------- stage C: fAcc += S2 @ Wf_g^T (M=64,N=256,K=128) ----
        auto loadC = [&](int k0) {
#pragma unroll
            for (int i = 0; i < 8; i++)
                rF[i] = *(const float4*)(g_Wfr + (size_t)(rb + i * 32) * 768 +
                                         gg * 128 + k0 + seg * 4);
        };
        auto stsC = [&]() {
#pragma unroll
            for (int i = 0; i < 8; i++)
                *(float4*)&Wfs[(rb + i * 32) * 36 + seg * 4] = rF[i];
        };

        loadC(0);
        stsC();  // safe: all threads passed stage-B final __syncthreads
        __syncthreads();  // makes S2 + Wfs visible to all
        for (int kc = 0; kc < 4; kc++) {
            if (kc + 1 < 4) loadC((kc + 1) * 32);
#pragma unroll
            for (int k8 = 0; k8 < 4; k8++) {
                const int kk = k8 * 8;
                unsigned a[2][4], b[8][2];
#pragma unroll
                for (int mt = 0; mt < 2; mt++) {
                    int r = wm * 32 + mt * 16 + qr;
                    int kcol = kc * 32 + kk + qc;
                    a[mt][0] = __float_as_uint(S2[r * 132 + kcol]);
                    a[mt][1] = __float_as_uint(S2[(r + 8) * 132 + kcol]);
                    a[mt][2] = __float_as_uint(S2[r * 132 + kcol + 4]);
                    a[mt][3] = __float_as_uint(S2[(r + 8) * 132 + kcol + 4]);
                }
#pragma unroll
                for (int nt = 0; nt < 8; nt++) {
                    int n = wn * 64 + nt * 8 + qr;
                    b[nt][0] = __float_as_uint(Wfs[n * 36 + kk + qc]);
                    b[nt][1] = __float_as_uint(Wfs[n * 36 + kk + qc + 4]);
                }
#pragma unroll
                for (int mt = 0; mt < 2; mt++)
#pragma unroll
                    for (int nt = 0; nt < 8; nt++) mma8(fAcc[mt][nt], a[mt], b[nt]);
            }
            __syncthreads();
            if (kc + 1 < 4) stsC();
            __syncthreads();
        }
    }

    // Final: bias + relu -> out
#pragma unroll
    for (int nt = 0; nt < 8; nt++) {
        int col = wn * 64 + nt * 8 + 2 * qc;
        float bb0 = bf[col], bb1 = bf[col + 1];
#pragma unroll
        for (int mt = 0; mt < 2; mt++) {
            int r = row0 + wm * 32 + mt * 16 + qr;
            if (r < N) {
                float2 s = make_float2(fmaxf(fAcc[mt][nt][0] + bb0, 0.f),
                                       fmaxf(fAcc[mt][nt][1] + bb1, 0.f));
                *(float2*)&out[(size_t)r * 256 + col] = s;
            }
            if (r + 8 < N) {
                float2 s = make_float2(fmaxf(fAcc[mt][nt][2] + bb0, 0.f),
                                       fmaxf(fAcc[mt][nt][3] + bb1, 0.f));
                *(float2*)&out[(size_t)(r + 8) * 256 + col] = s;
            }
        }
    }
}

// ---------------------------------------------------------------------------
// kernel_launch
// ---------------------------------------------------------------------------
extern "C" void kernel_launch(void* const* d_in, const int* in_sizes, int n_in,
                              void* d_out, int out_size) {
    const float* upd = (const float*)d_in[0];
    const float* W10 = (const float*)d_in[1];
    const float* b10 = (const float*)d_in[2];
    const float* W1  = (const float*)d_in[3];
    const float* b1  = (const float*)d_in[4];
    const float* W2  = (const float*)d_in[5];
    const float* b2  = (const float*)d_in[6];
    const float* Wf  = (const float*)d_in[7];
    const float* bf  = (const float*)d_in[8];
    int N = in_sizes[0] / (17 * 256);

    const int smem2 = (8448 + 9216) * 4;  // 70656 bytes
    cudaFuncSetAttribute(stage23_kernel, cudaFuncAttributeMaxDynamicSharedMemorySize,
                         smem2);

    round_weights_kernel<<<256, 256>>>(W10, W1, W2, Wf);

    int t1 = (N + 127) / 128;
    stage1_kernel<<<dim3(t1, 7), 256>>>(upd, b10, b1, N);

    int t2 = (N + 63) / 64;
    stage23_kernel<<<t2, 256, smem2>>>(b2, bf, (float*)d_out, N);
}

// round 5
// speedup vs baseline: 1.2035x; 1.2035x over previous
#include <cuda_runtime.h>
#include <cstdint>

// ---------------------------------------------------------------------------
// HierarchUpdateMlp — legacy mma.sync tf32 (tcgen05 unavailable: harness PTX
// target is sm_103 without the 'a' feature suffix).
//   prepass : rna-round all weights into scratch
//   k<0>    : stage A, 7 GEMMs (M=256 tile, N=128, K=1280/512) -> g_out1
//   k<1>    : stage B, 6 GEMMs (K=256, pair gather from g_out1) -> g_out2
//   k<2>    : stage C, GEMM (N=256 via 2 halves, K=768) -> out
// All GEMMs: CTA 256x128, 8 warps (4m x 2n), warp 64x64, K-chunk 32,
// 3-stage cp.async pipeline, stride-36 padded smem (conflict-free fragments).
// ---------------------------------------------------------------------------

#define NPAD 50176  // ceil(50000/256)*256

__device__ __align__(16) float g_out1[(size_t)NPAD * 896];
__device__ __align__(16) float g_out2[(size_t)NPAD * 768];
__device__ __align__(16) float g_W10r[128 * 1280];
__device__ __align__(16) float g_W1r[6 * 128 * 512];
__device__ __align__(16) float g_W2r[6 * 128 * 256];
__device__ __align__(16) float g_Wfr[256 * 768];

__device__ __forceinline__ float f2tff(float x) {
    unsigned u;
    asm("cvt.rna.tf32.f32 %0, %1;" : "=r"(u) : "f"(x));
    return __uint_as_float(u);
}
__device__ __forceinline__ uint32_t smaddr(const void* p) {
    uint32_t a;
    asm("{ .reg .u64 t; cvta.to.shared.u64 t, %1; cvt.u32.u64 %0, t; }"
        : "=r"(a) : "l"(p));
    return a;
}
__device__ __forceinline__ void cpa_cg(uint32_t d, const float* s) {
    asm volatile("cp.async.cg.shared.global [%0], [%1], 16;" :: "r"(d), "l"(s)
                 : "memory");
}
__device__ __forceinline__ void cpa_ca(uint32_t d, const float* s) {
    asm volatile("cp.async.ca.shared.global [%0], [%1], 16;" :: "r"(d), "l"(s)
                 : "memory");
}
__device__ __forceinline__ void cp_commit() {
    asm volatile("cp.async.commit_group;" ::: "memory");
}
__device__ __forceinline__ void cp_wait(int allowed) {
    if (allowed >= 2) asm volatile("cp.async.wait_group 2;" ::: "memory");
    else if (allowed == 1) asm volatile("cp.async.wait_group 1;" ::: "memory");
    else asm volatile("cp.async.wait_group 0;" ::: "memory");
}
__device__ __forceinline__ void mma8(float (&c)[4], const unsigned (&a)[4],
                                     const unsigned (&b)[2]) {
    asm volatile(
        "mma.sync.aligned.m16n8k8.row.col.f32.tf32.tf32.f32 "
        "{%0,%1,%2,%3},{%4,%5,%6,%7},{%8,%9},{%0,%1,%2,%3};\n"
        : "+f"(c[0]), "+f"(c[1]), "+f"(c[2]), "+f"(c[3])
        : "r"(a[0]), "r"(a[1]), "r"(a[2]), "r"(a[3]), "r"(b[0]), "r"(b[1]));
}

// ---------------------------------------------------------------------------
// Prepass: rna-round weights into scratch.
// ---------------------------------------------------------------------------
__global__ void round_weights_kernel(const float* __restrict__ W10,
                                     const float* __restrict__ W1,
                                     const float* __restrict__ W2,
                                     const float* __restrict__ Wf) {
    int i = blockIdx.x * blockDim.x + threadIdx.x;
    int st = gridDim.x * blockDim.x;
    for (int j = i; j < 128 * 1280; j += st) g_W10r[j] = f2tff(W10[j]);
    for (int j = i; j < 6 * 128 * 512; j += st) g_W1r[j] = f2tff(W1[j]);
    for (int j = i; j < 6 * 128 * 256; j += st) g_W2r[j] = f2tff(W2[j]);
    for (int j = i; j < 256 * 768; j += st) g_Wfr[j] = f2tff(Wf[j]);
}

// ---------------------------------------------------------------------------
// Unified GEMM kernel. Smem: 3 stages x (A 256x36 + B 128x36) floats.
// MODE 0: A=update (joint gather, fragment cvt), B=g_W10r/g_W1r, out=g_out1
// MODE 1: A=g_out1 (pair gather),                B=g_W2r,       out=g_out2
// MODE 2: A=g_out2 (contiguous),                 B=g_Wfr,       out=dst
// ---------------------------------------------------------------------------
#define STG_FLTS 13824  // (256+128)*36

template <int MODE>
__global__ __launch_bounds__(256, 1)
void gemm_k(const float* __restrict__ Ain, const float* __restrict__ bias0,
            const float* __restrict__ bias1, float* __restrict__ dstp, int N) {
    extern __shared__ __align__(16) float sm[];

    const int tid = threadIdx.x;
    const int lane = tid & 31, warp = tid >> 5;
    const int wm = warp >> 1, wn = warp & 1;
    const int qr = lane >> 2, qc = lane & 3;
    const int row0 = blockIdx.x * 256;
    const int g = blockIdx.y;

    int K, ldB, ldA, ldO, colO, j1 = 0, j2 = 0, c1 = 0, c2 = 0;
    const float *Bsrc, *bias, *Asrc;
    float* Dst;
    if (MODE == 0) {
        if (g == 0) { K = 1280; Bsrc = g_W10r; ldB = 1280; bias = bias0; }
        else {
            const int p1[6] = {5, 7, 8, 11, 13, 14};
            const int p2[6] = {6, 9, 10, 12, 15, 16};
            K = 512; Bsrc = g_W1r + (size_t)(g - 1) * 65536; ldB = 512;
            bias = bias1 + (g - 1) * 128;
            j1 = p1[g - 1]; j2 = p2[g - 1];
        }
        Asrc = Ain; ldA = 4352; Dst = g_out1; ldO = 896; colO = g * 128;
    } else if (MODE == 1) {
        const int q1[6] = {0, 1, 1, 1, 4, 4};
        const int q2[6] = {1, 2, 3, 4, 5, 6};
        K = 256; Bsrc = g_W2r + (size_t)g * 32768; ldB = 256;
        bias = bias0 + g * 128;
        c1 = q1[g] * 128; c2 = q2[g] * 128;
        Asrc = g_out1; ldA = 896; Dst = g_out2; ldO = 768; colO = g * 128;
    } else {
        K = 768; Bsrc = g_Wfr + (size_t)g * 98304; ldB = 768;
        bias = bias0 + g * 128;
        Asrc = g_out2; ldA = 768; Dst = dstp; ldO = 256; colO = g * 128;
    }
    const int nk = K >> 5;

    float acc[4][8][4];
#pragma unroll
    for (int i = 0; i < 4; i++)
#pragma unroll
        for (int j = 0; j < 8; j++)
#pragma unroll
            for (int k = 0; k < 4; k++) acc[i][j][k] = 0.f;

    const uint32_t smb = smaddr(sm);

    auto issue = [&](int ci) {
        const int k0 = ci * 32;
        const uint32_t Ab = smb + (uint32_t)(ci % 3) * (STG_FLTS * 4);
        const uint32_t Bb = Ab + 9216 * 4;
        int joff;
        if (MODE == 0)
            joff = (g == 0) ? k0 : (((k0 < 256) ? j1 : j2) * 256 + (k0 & 255));
        else if (MODE == 1)
            joff = (k0 < 128) ? (c1 + k0) : (c2 + k0 - 128);
        else
            joff = k0;
#pragma unroll
        for (int u = 0; u < 8; u++) {
            const int idx = tid + u * 256, row = idx >> 3, seg = idx & 7;
            int r = row0 + row;
            if (r > N - 1) r = N - 1;
            cpa_cg(Ab + (uint32_t)(row * 36 + seg * 4) * 4,
                   Asrc + (size_t)r * ldA + joff + seg * 4);
        }
#pragma unroll
        for (int u = 0; u < 4; u++) {
            const int idx = tid + u * 256, row = idx >> 3, seg = idx & 7;
            cpa_ca(Bb + (uint32_t)(row * 36 + seg * 4) * 4,
                   Bsrc + (size_t)row * ldB + k0 + seg * 4);
        }
        cp_commit();
    };

    issue(0); issue(1); issue(2);

    for (int i = 0; i < nk; i++) {
        int rem = nk - 1 - i;
        cp_wait(rem < 2 ? rem : 2);
        __syncthreads();

        const float* As = sm + (i % 3) * STG_FLTS;
        const float* Bs = As + 9216;
#pragma unroll
        for (int k8 = 0; k8 < 4; k8++) {
            const int kk = k8 * 8;
            unsigned a[4][4], b[8][2];
#pragma unroll
            for (int mt = 0; mt < 4; mt++) {
                const int r = wm * 64 + mt * 16 + qr;
                float a0 = As[r * 36 + kk + qc];
                float a1 = As[(r + 8) * 36 + kk + qc];
                float a2 = As[r * 36 + kk + qc + 4];
                float a3 = As[(r + 8) * 36 + kk + qc + 4];
                if (MODE == 0) {
                    a0 = f2tff(a0); a1 = f2tff(a1);
                    a2 = f2tff(a2); a3 = f2tff(a3);
                }
                a[mt][0] = __float_as_uint(a0);
                a[mt][1] = __float_as_uint(a1);
                a[mt][2] = __float_as_uint(a2);
                a[mt][3] = __float_as_uint(a3);
            }
#pragma unroll
            for (int nt = 0; nt < 8; nt++) {
                const int n = wn * 64 + nt * 8 + qr;
                b[nt][0] = __float_as_uint(Bs[n * 36 + kk + qc]);
                b[nt][1] = __float_as_uint(Bs[n * 36 + kk + qc + 4]);
            }
#pragma unroll
            for (int mt = 0; mt < 4; mt++)
#pragma unroll
                for (int nt = 0; nt < 8; nt++) mma8(acc[mt][nt], a[mt], b[nt]);
        }
        __syncthreads();
        if (i + 3 < nk) issue(i + 3);
    }

    // Epilogue: bias + relu (+rna for intermediates), direct STG.
#pragma unroll
    for (int mt = 0; mt < 4; mt++) {
        const int r0 = row0 + wm * 64 + mt * 16 + qr;
#pragma unroll
        for (int nt = 0; nt < 8; nt++) {
            const int lc = wn * 64 + nt * 8 + 2 * qc;
            const float bb0 = __ldg(bias + lc);
            const float bb1 = __ldg(bias + lc + 1);
            float v0 = fmaxf(acc[mt][nt][0] + bb0, 0.f);
            float v1 = fmaxf(acc[mt][nt][1] + bb1, 0.f);
            float v2 = fmaxf(acc[mt][nt][2] + bb0, 0.f);
            float v3 = fmaxf(acc[mt][nt][3] + bb1, 0.f);
            if (MODE < 2) {
                v0 = f2tff(v0); v1 = f2tff(v1); v2 = f2tff(v2); v3 = f2tff(v3);
            }
            if (r0 < N)
                *(float2*)&Dst[(size_t)r0 * ldO + colO + lc] = make_float2(v0, v1);
            if (r0 + 8 < N)
                *(float2*)&Dst[(size_t)(r0 + 8) * ldO + colO + lc] =
                    make_float2(v2, v3);
        }
    }
}

// ---------------------------------------------------------------------------
// kernel_launch
// ---------------------------------------------------------------------------
extern "C" void kernel_launch(void* const* d_in, const int* in_sizes, int n_in,
                              void* d_out, int out_size) {
    const float* upd = (const float*)d_in[0];
    const float* W10 = (const float*)d_in[1];
    const float* b10 = (const float*)d_in[2];
    const float* W1  = (const float*)d_in[3];
    const float* b1  = (const float*)d_in[4];
    const float* W2  = (const float*)d_in[5];
    const float* b2  = (const float*)d_in[6];
    const float* Wf  = (const float*)d_in[7];
    const float* bf  = (const float*)d_in[8];
    const int N = in_sizes[0] / (17 * 256);

    const int smem = 3 * STG_FLTS * 4;  // 165888 B
    static int attr_done = 0;
    cudaFuncSetAttribute(gemm_k<0>, cudaFuncAttributeMaxDynamicSharedMemorySize, smem);
    cudaFuncSetAttribute(gemm_k<1>, cudaFuncAttributeMaxDynamicSharedMemorySize, smem);
    cudaFuncSetAttribute(gemm_k<2>, cudaFuncAttributeMaxDynamicSharedMemorySize, smem);
    (void)attr_done;

    round_weights_kernel<<<256, 256>>>(W10, W1, W2, Wf);

    const int tiles = (N + 255) / 256;
    gemm_k<0><<<dim3(tiles, 7), 256, smem>>>(upd, b10, b1, nullptr, N);
    gemm_k<1><<<dim3(tiles, 6), 256, smem>>>(nullptr, b2, nullptr, nullptr, N);
    gemm_k<2><<<dim3(tiles, 2), 256, smem>>>(nullptr, bf, nullptr, (float*)d_out, N);
}